// round 3
// baseline (speedup 1.0000x reference)
#include <cuda_runtime.h>
#include <math.h>

#define NB 8
#define NL 1024
#define NS 1024
#define NG 64
#define ND 1024
#define NH 16
#define DH 64

// ---------------- scratch (device globals: no allocations allowed) ----------
__device__ float g_q  [NB*NH*NL*DH];   // (B,H,L,64)  -> becomes qe in-place
__device__ float g_k  [NB*NH*NS*DH];   // (B,H,S,64)
__device__ float g_v  [NB*NH*NS*DH];   // (B,H,S,64)
__device__ float g_rq [NB*NH*NG*DH];   // (B,H,G,64)
__device__ float g_rk [NB*NH*NG*DH];   // (B,H,G,64)
__device__ float g_wep[NB*NH*DH*DH];   // (B,H,64,64) (scale folded in)
__device__ float g_ot [NB*ND*NL];      // (B, H*64, L)  transposed attn output

// ---------------- generic 128x128x16 SGEMM, K=N=1024 ------------------------
// MODE 0: plain output Y[m*1024+n] + bias[n]
// MODE 1: head-split output: b=m/Ntok, t=m%Ntok, h=n/64, d=n%64
//         Y[((b*NH+h)*Ntok + t)*64 + d]
template<int MODE>
__global__ void __launch_bounds__(256) sgemm128(
    const float* __restrict__ A, const float* __restrict__ W,
    float* __restrict__ Y, const float* __restrict__ bias, int Ntok)
{
    __shared__ float As[16][128];
    __shared__ float Bs[16][128];
    const int tid = threadIdx.x;
    const int m0 = blockIdx.x * 128;
    const int n0 = blockIdx.y * 128;
    const int tx = tid & 15, ty = tid >> 4;

    float acc[8][8];
#pragma unroll
    for (int i = 0; i < 8; i++)
#pragma unroll
        for (int j = 0; j < 8; j++) acc[i][j] = 0.f;

    const int ar = tid >> 2;          // 0..63
    const int ac = (tid & 3) << 2;    // 0,4,8,12
    const int br = tid >> 5;          // 0..7
    const int bc = (tid & 31) << 2;   // 0..124

    for (int k0 = 0; k0 < 1024; k0 += 16) {
#pragma unroll
        for (int i = 0; i < 2; i++) {
            float4 va = *(const float4*)&A[(m0 + ar + i*64)*1024 + k0 + ac];
            As[ac+0][ar + i*64] = va.x;
            As[ac+1][ar + i*64] = va.y;
            As[ac+2][ar + i*64] = va.z;
            As[ac+3][ar + i*64] = va.w;
        }
#pragma unroll
        for (int i = 0; i < 2; i++) {
            *(float4*)&Bs[br + i*8][bc] =
                *(const float4*)&W[(k0 + br + i*8)*1024 + n0 + bc];
        }
        __syncthreads();
#pragma unroll
        for (int kk = 0; kk < 16; kk++) {
            float a[8], b[8];
            *(float4*)&a[0] = *(float4*)&As[kk][ty*8];
            *(float4*)&a[4] = *(float4*)&As[kk][ty*8+4];
            *(float4*)&b[0] = *(float4*)&Bs[kk][tx*8];
            *(float4*)&b[4] = *(float4*)&Bs[kk][tx*8+4];
#pragma unroll
            for (int i = 0; i < 8; i++)
#pragma unroll
                for (int j = 0; j < 8; j++)
                    acc[i][j] = fmaf(a[i], b[j], acc[i][j]);
        }
        __syncthreads();
    }

#pragma unroll
    for (int i = 0; i < 8; i++) {
        int m = m0 + ty*8 + i;
#pragma unroll
        for (int j4 = 0; j4 < 8; j4 += 4) {
            int n = n0 + tx*8 + j4;
            float4 r;
            r.x = acc[i][j4+0]; r.y = acc[i][j4+1];
            r.z = acc[i][j4+2]; r.w = acc[i][j4+3];
            if (MODE == 0) {
                float4 bb = *(const float4*)&bias[n];
                r.x += bb.x; r.y += bb.y; r.z += bb.z; r.w += bb.w;
                *(float4*)&Y[m*1024 + n] = r;
            } else {
                int b = m / Ntok, t = m - b*Ntok;
                int h = n >> 6, d = n & 63;
                *(float4*)&Y[(((b*NH + h)*Ntok + t) << 6) + d] = r;
            }
        }
    }
}

// ---------------- W_ep[b,h] = rq^T @ rk * scale ------------------------------
__global__ void __launch_bounds__(256) wep_kernel(
    const float* __restrict__ rq, const float* __restrict__ rk,
    float* __restrict__ wep)
{
    __shared__ float sq[64][65];
    __shared__ float sk[64][65];
    const int bh = blockIdx.x;
    const float* rqb = rq + (bh << 12);
    const float* rkb = rk + (bh << 12);
    const int tid = threadIdx.x;
#pragma unroll
    for (int i = 0; i < 4; i++) {
        int idx = (tid + i*256) << 2;
        int r = idx >> 6, c = idx & 63;
        float4 a = *(const float4*)&rqb[idx];
        float4 b = *(const float4*)&rkb[idx];
        sq[r][c] = a.x; sq[r][c+1] = a.y; sq[r][c+2] = a.z; sq[r][c+3] = a.w;
        sk[r][c] = b.x; sk[r][c+1] = b.y; sk[r][c+2] = b.z; sk[r][c+3] = b.w;
    }
    __syncthreads();
    const int tx = tid & 15, ty = tid >> 4;
    float acc[4][4];
#pragma unroll
    for (int i = 0; i < 4; i++)
#pragma unroll
        for (int j = 0; j < 4; j++) acc[i][j] = 0.f;
    for (int g = 0; g < 64; g++) {
        float a[4], b[4];
#pragma unroll
        for (int i = 0; i < 4; i++) a[i] = sq[g][ty*4+i];
#pragma unroll
        for (int j = 0; j < 4; j++) b[j] = sk[g][tx*4+j];
#pragma unroll
        for (int i = 0; i < 4; i++)
#pragma unroll
            for (int j = 0; j < 4; j++)
                acc[i][j] = fmaf(a[i], b[j], acc[i][j]);
    }
    const float scale = 0.125f;  // 1/sqrt(64)
#pragma unroll
    for (int i = 0; i < 4; i++) {
        float4 r4 = make_float4(acc[i][0]*scale, acc[i][1]*scale,
                                acc[i][2]*scale, acc[i][3]*scale);
        *(float4*)&wep[(bh << 12) + (ty*4+i)*64 + tx*4] = r4;
    }
}

// ---------------- q <- q @ W_ep (in place, per (b,h)) ------------------------
__global__ void __launch_bounds__(256) qfold_kernel(
    float* __restrict__ q, const float* __restrict__ wep)
{
    __shared__ float sq[64][65];
    __shared__ float sw[64][68];
    const int bh = blockIdx.y;
    const int l0 = blockIdx.x * 64;
    float* qb = q + (((size_t)bh * NL + l0) << 6);
    const float* wb = wep + (bh << 12);
    const int tid = threadIdx.x;
#pragma unroll
    for (int i = 0; i < 4; i++) {
        int idx = (tid + i*256) << 2;
        int r = idx >> 6, c = idx & 63;
        float4 vq = *(const float4*)&qb[idx];
        sq[r][c] = vq.x; sq[r][c+1] = vq.y; sq[r][c+2] = vq.z; sq[r][c+3] = vq.w;
        *(float4*)&sw[r][c] = *(const float4*)&wb[idx];
    }
    __syncthreads();
    const int tx = tid & 15, ty = tid >> 4;
    float acc[4][4];
#pragma unroll
    for (int i = 0; i < 4; i++)
#pragma unroll
        for (int j = 0; j < 4; j++) acc[i][j] = 0.f;
    for (int d = 0; d < 64; d++) {
        float a[4];
#pragma unroll
        for (int i = 0; i < 4; i++) a[i] = sq[ty*4+i][d];
        float4 wv = *(float4*)&sw[d][tx*4];
#pragma unroll
        for (int i = 0; i < 4; i++) {
            acc[i][0] = fmaf(a[i], wv.x, acc[i][0]);
            acc[i][1] = fmaf(a[i], wv.y, acc[i][1]);
            acc[i][2] = fmaf(a[i], wv.z, acc[i][2]);
            acc[i][3] = fmaf(a[i], wv.w, acc[i][3]);
        }
    }
    // all global reads are done (staged through smem) -> in-place write is safe
#pragma unroll
    for (int i = 0; i < 4; i++) {
        float4 r4 = make_float4(acc[i][0], acc[i][1], acc[i][2], acc[i][3]);
        *(float4*)&qb[((ty*4+i) << 6) + tx*4] = r4;
    }
}

// ---------------- flash attention: per (b,h), 64 q-rows per block -----------
// scores = qe @ k^T (scale already folded), online softmax, O = P @ V.
// Writes O transposed:  ot[b,h,d,l]  (layout (B, H*64, L)) for the final GEMM.
__global__ void __launch_bounds__(256) attn_kernel(
    const float* __restrict__ q, const float* __restrict__ k,
    const float* __restrict__ v, float* __restrict__ ot)
{
    __shared__ float s_qe[64][68];
    __shared__ float s_k [32][68];
    __shared__ float s_v [32][68];
    __shared__ float s_p [64][36];

    const int bh = blockIdx.y;
    const int l0 = blockIdx.x * 64;
    const float* qb = q + (((size_t)bh * NL + l0) << 6);
    const float* kb = k + (((size_t)bh * NS) << 6);
    const float* vb = v + (((size_t)bh * NS) << 6);
    float* otb = ot + (size_t)(bh << 6) * NL;

    const int tid = threadIdx.x;
    const int tx = tid & 15, ty = tid >> 4;

    // load qe tile (64x64)
#pragma unroll
    for (int i = 0; i < 4; i++) {
        int idx = (tid + i*256) << 2;
        int r = idx >> 6, c = idx & 63;
        *(float4*)&s_qe[r][c] = *(const float4*)&qb[idx];
    }

    float o[4][4];
#pragma unroll
    for (int i = 0; i < 4; i++)
#pragma unroll
        for (int j = 0; j < 4; j++) o[i][j] = 0.f;
    float mrow[4] = {-1e30f, -1e30f, -1e30f, -1e30f};
    float lrow[4] = {0.f, 0.f, 0.f, 0.f};

    for (int s0 = 0; s0 < NS; s0 += 32) {
        // load K,V chunk (32x64 each)
#pragma unroll
        for (int i = 0; i < 2; i++) {
            int idx = (tid + i*256) << 2;
            int r = idx >> 6, c = idx & 63;
            *(float4*)&s_k[r][c] = *(const float4*)&kb[(s0 << 6) + idx];
            *(float4*)&s_v[r][c] = *(const float4*)&vb[(s0 << 6) + idx];
        }
        __syncthreads();   // also orders the qe-tile stores on first iter

        // scores: rows ty*4+i (64), cols tx*2+j (32)
        float sc[4][2];
#pragma unroll
        for (int i = 0; i < 4; i++) { sc[i][0] = 0.f; sc[i][1] = 0.f; }
#pragma unroll
        for (int d4 = 0; d4 < 64; d4 += 4) {
            float qa[4][4], kk2[2][4];
#pragma unroll
            for (int i = 0; i < 4; i++)
                *(float4*)qa[i] = *(float4*)&s_qe[ty*4+i][d4];
#pragma unroll
            for (int j = 0; j < 2; j++)
                *(float4*)kk2[j] = *(float4*)&s_k[tx*2+j][d4];
#pragma unroll
            for (int i = 0; i < 4; i++)
#pragma unroll
                for (int j = 0; j < 2; j++)
#pragma unroll
                    for (int d = 0; d < 4; d++)
                        sc[i][j] = fmaf(qa[i][d], kk2[j][d], sc[i][j]);
        }

        // online softmax (row reductions across the 16 tx lanes)
#pragma unroll
        for (int i = 0; i < 4; i++) {
            float mx = fmaxf(sc[i][0], sc[i][1]);
#pragma unroll
            for (int off = 8; off >= 1; off >>= 1)
                mx = fmaxf(mx, __shfl_xor_sync(0xffffffffu, mx, off));
            float mnew = fmaxf(mrow[i], mx);
            float fac  = __expf(mrow[i] - mnew);
            mrow[i] = mnew;
            float rs = 0.f;
#pragma unroll
            for (int j = 0; j < 2; j++) {
                sc[i][j] = __expf(sc[i][j] - mnew);
                rs += sc[i][j];
            }
#pragma unroll
            for (int off = 8; off >= 1; off >>= 1)
                rs += __shfl_xor_sync(0xffffffffu, rs, off);
            lrow[i] = lrow[i]*fac + rs;
#pragma unroll
            for (int j = 0; j < 4; j++) o[i][j] *= fac;
            s_p[ty*4+i][tx*2+0] = sc[i][0];
            s_p[ty*4+i][tx*2+1] = sc[i][1];
        }
        __syncthreads();

        // O += P @ V : o[r=ty*4+i][d=tx*4+j]
#pragma unroll
        for (int c4 = 0; c4 < 32; c4 += 4) {
            float pa[4][4], vv[4][4];
#pragma unroll
            for (int i = 0; i < 4; i++)
                *(float4*)pa[i] = *(float4*)&s_p[ty*4+i][c4];
#pragma unroll
            for (int cc = 0; cc < 4; cc++)
                *(float4*)vv[cc] = *(float4*)&s_v[c4+cc][tx*4];
#pragma unroll
            for (int i = 0; i < 4; i++)
#pragma unroll
                for (int j = 0; j < 4; j++)
#pragma unroll
                    for (int cc = 0; cc < 4; cc++)
                        o[i][j] = fmaf(pa[i][cc], vv[cc][j], o[i][j]);
        }
        __syncthreads();
    }

    // normalize + transpose via smem staging (pitch 65 -> conflict-free)
    float* st = &s_qe[0][0];
#pragma unroll
    for (int i = 0; i < 4; i++) {
        float inv = 1.f / lrow[i];
#pragma unroll
        for (int j = 0; j < 4; j++)
            st[(ty*4+i)*65 + tx*4+j] = o[i][j] * inv;
    }
    __syncthreads();
#pragma unroll
    for (int it = 0; it < 16; it++) {
        int idx = tid + it*256;
        int d = idx >> 6, l = idx & 63;
        otb[d*NL + l0 + l] = st[l*65 + d];
    }
}

// ---------------- launch -----------------------------------------------------
extern "C" void kernel_launch(void* const* d_in, const int* in_sizes, int n_in,
                              void* d_out, int out_size)
{
    const float* queries = (const float*)d_in[0];
    const float* keys    = (const float*)d_in[1];
    const float* values  = (const float*)d_in[2];
    const float* routers = (const float*)d_in[3];
    const float* Wq  = (const float*)d_in[4];
    const float* Wk  = (const float*)d_in[5];
    const float* Wv  = (const float*)d_in[6];
    const float* Wlq = (const float*)d_in[7];
    const float* Wlk = (const float*)d_in[8];
    const float* Wo  = (const float*)d_in[9];
    const float* bo  = (const float*)d_in[10];

    float *q, *k, *v, *rq, *rk, *wep, *ot;
    cudaGetSymbolAddress((void**)&q,   g_q);
    cudaGetSymbolAddress((void**)&k,   g_k);
    cudaGetSymbolAddress((void**)&v,   g_v);
    cudaGetSymbolAddress((void**)&rq,  g_rq);
    cudaGetSymbolAddress((void**)&rk,  g_rk);
    cudaGetSymbolAddress((void**)&wep, g_wep);
    cudaGetSymbolAddress((void**)&ot,  g_ot);

    dim3 blk(256);
    sgemm128<1><<<dim3(64, 8), blk>>>(queries, Wq,  q,  nullptr, NL);
    sgemm128<1><<<dim3(64, 8), blk>>>(keys,    Wk,  k,  nullptr, NS);
    sgemm128<1><<<dim3(64, 8), blk>>>(values,  Wv,  v,  nullptr, NS);
    sgemm128<1><<<dim3(4, 8),  blk>>>(routers, Wlq, rq, nullptr, NG);
    sgemm128<1><<<dim3(4, 8),  blk>>>(routers, Wlk, rk, nullptr, NG);
    wep_kernel <<<128, blk>>>(rq, rk, wep);
    qfold_kernel<<<dim3(16, 128), blk>>>(q, wep);
    attn_kernel <<<dim3(16, 128), blk>>>(q, k, v, ot);
    sgemm128<0><<<dim3(64, 8), blk>>>(ot, Wo, (float*)d_out, bo, NL);
}